// round 1
// baseline (speedup 1.0000x reference)
#include <cuda_runtime.h>
#include <math.h>

// Problem constants
#define T_SEQ 128
#define B_SZ  32
#define H_SZ  512
#define V_SZ  32000
#define G3    1536          // 3*H
#define M_ROWS 4096         // B*T

// Scratch (device globals: allocation-free rule)
__device__ float g_xg[(size_t)M_ROWS * G3];        // [m = b*T+t][3H]
__device__ float g_hs[(size_t)T_SEQ * B_SZ * H_SZ]; // [t][b][h]

// ---------- packed fp32x2 helpers (sm_10x FFMA2 path, PTX-only) ----------
static __device__ __forceinline__ unsigned long long pk2(float lo, float hi) {
    unsigned long long r;
    asm("mov.b64 %0, {%1, %2};" : "=l"(r) : "f"(lo), "f"(hi));
    return r;
}
static __device__ __forceinline__ unsigned long long f2fma(unsigned long long a,
                                                           unsigned long long b,
                                                           unsigned long long c) {
    unsigned long long d;
    asm("fma.rn.f32x2 %0, %1, %2, %3;" : "=l"(d) : "l"(a), "l"(b), "l"(c));
    return d;
}
static __device__ __forceinline__ float2 upk2(unsigned long long v) {
    float2 r;
    asm("mov.b64 {%0, %1}, %2;" : "=f"(r.x), "=f"(r.y) : "l"(v));
    return r;
}

static __device__ __forceinline__ float sigmoidf_(float x) {
    return 1.0f / (1.0f + expf(-x));
}

// =====================================================================
// Kernel 1: embed + input-gate GEMM
//   xg[m, g] = sum_k emb[tok(m), k] * w_ih[g, k] + b_ih[g]
//   tok(m):  t = m & 127; t==0 -> START(=1), else target[m-1]
// Tiling: 128x128x16, 256 threads, 8x8/thread via f32x2.
// =====================================================================
#define BM 128
#define BN 128
#define BK 16
#define LDS_STRIDE 132   // BM + 4 pad (keeps 16B alignment, breaks conflicts)

__global__ __launch_bounds__(256, 2)
void embed_xg_kernel(const float* __restrict__ emb,
                     const float* __restrict__ w_ih,
                     const float* __restrict__ b_ih,
                     const int*   __restrict__ target)
{
    __shared__ float As[BK * LDS_STRIDE];  // [k][m]
    __shared__ float Bs[BK * LDS_STRIDE];  // [k][n]

    const int tid = threadIdx.x;
    const int tx = tid & 15;      // 0..15 -> n groups of 8
    const int ty = tid >> 4;      // 0..15 -> m groups of 8
    const int m0 = blockIdx.x * BM;
    const int n0 = blockIdx.y * BN;

    unsigned long long acc[8][4];
#pragma unroll
    for (int i = 0; i < 8; i++)
#pragma unroll
        for (int j = 0; j < 4; j++) acc[i][j] = 0ull;

    for (int k0 = 0; k0 < H_SZ; k0 += BK) {
#pragma unroll
        for (int l = 0; l < 2; l++) {
            int f4  = tid + l * 256;        // 0..511
            int row = f4 >> 2;              // 0..127
            int c   = (f4 & 3) << 2;        // 0,4,8,12
            // A: gathered embedding row
            int m = m0 + row;
            int tok = (m & (T_SEQ - 1)) ? target[m - 1] : 1;
            float4 v = *(const float4*)(emb + (size_t)tok * H_SZ + k0 + c);
            As[(c + 0) * LDS_STRIDE + row] = v.x;
            As[(c + 1) * LDS_STRIDE + row] = v.y;
            As[(c + 2) * LDS_STRIDE + row] = v.z;
            As[(c + 3) * LDS_STRIDE + row] = v.w;
            // B: w_ih row (NT gemm, K contiguous)
            int g = n0 + row;
            float4 w = *(const float4*)(w_ih + (size_t)g * H_SZ + k0 + c);
            Bs[(c + 0) * LDS_STRIDE + row] = w.x;
            Bs[(c + 1) * LDS_STRIDE + row] = w.y;
            Bs[(c + 2) * LDS_STRIDE + row] = w.z;
            Bs[(c + 3) * LDS_STRIDE + row] = w.w;
        }
        __syncthreads();

#pragma unroll
        for (int kk = 0; kk < BK; kk++) {
            const float* Ak = &As[kk * LDS_STRIDE + ty * 8];
            float4 a0 = *(const float4*)(Ak);
            float4 a1 = *(const float4*)(Ak + 4);
            const float* Bk = &Bs[kk * LDS_STRIDE + tx * 8];
            ulonglong2 bl0 = *(const ulonglong2*)(Bk);
            ulonglong2 bl1 = *(const ulonglong2*)(Bk + 4);
            float av[8] = {a0.x, a0.y, a0.z, a0.w, a1.x, a1.y, a1.z, a1.w};
#pragma unroll
            for (int i = 0; i < 8; i++) {
                unsigned long long a2 = pk2(av[i], av[i]);
                acc[i][0] = f2fma(a2, bl0.x, acc[i][0]);
                acc[i][1] = f2fma(a2, bl0.y, acc[i][1]);
                acc[i][2] = f2fma(a2, bl1.x, acc[i][2]);
                acc[i][3] = f2fma(a2, bl1.y, acc[i][3]);
            }
        }
        __syncthreads();
    }

    const int gcol = n0 + tx * 8;
    float4 bi0 = *(const float4*)(b_ih + gcol);
    float4 bi1 = *(const float4*)(b_ih + gcol + 4);
#pragma unroll
    for (int i = 0; i < 8; i++) {
        int m = m0 + ty * 8 + i;
        float2 p0 = upk2(acc[i][0]);
        float2 p1 = upk2(acc[i][1]);
        float2 p2 = upk2(acc[i][2]);
        float2 p3 = upk2(acc[i][3]);
        float4 o0 = {p0.x + bi0.x, p0.y + bi0.y, p1.x + bi0.z, p1.y + bi0.w};
        float4 o1 = {p2.x + bi1.x, p2.y + bi1.y, p3.x + bi1.z, p3.y + bi1.w};
        float* dst = g_xg + (size_t)m * G3 + gcol;
        *(float4*)(dst)     = o0;
        *(float4*)(dst + 4) = o1;
    }
}

// =====================================================================
// Kernel 2: one GRU step (launched 128x, stream-ordered)
//   grid 128 CTAs: CTA owns H dims [cta*4, cta*4+4) for all 32 batches.
//   SMEM-caches its 12 w_hh rows (r,z,n x 4 dims).
//   block 128 threads: thread = (b = tid>>2, il = tid&3)
// =====================================================================
#define WS_STRIDE 516   // 512 + 4 pad

__global__ __launch_bounds__(128)
void gru_step_kernel(int t,
                     const float* __restrict__ w_hh,
                     const float* __restrict__ b_hh,
                     const float* __restrict__ enc)
{
    __shared__ float ws[12 * WS_STRIDE];

    const int cta = blockIdx.x;     // 0..127
    const int tid = threadIdx.x;

    const float* h_prev = (t == 0) ? enc : (g_hs + (size_t)(t - 1) * B_SZ * H_SZ);

    // Cooperative load of 12 w_hh rows (rows: gate*512 + cta*4 + il)
#pragma unroll
    for (int l = 0; l < 12; l++) {
        int f4 = tid + l * 128;          // 0..1535 float4 slots
        int r  = f4 >> 7;                // 0..11 (128 float4 per row)
        int c  = (f4 & 127) << 2;        // 0..508
        int gate = r >> 2;
        int il   = r & 3;
        int grow = gate * H_SZ + cta * 4 + il;
        *(float4*)&ws[r * WS_STRIDE + c] =
            *(const float4*)(w_hh + (size_t)grow * H_SZ + c);
    }
    __syncthreads();

    const int b  = tid >> 2;
    const int il = tid & 3;
    const int i  = cta * 4 + il;

    const float* hp = h_prev + b * H_SZ;
    const float* wr = &ws[(0 + il) * WS_STRIDE];
    const float* wz = &ws[(4 + il) * WS_STRIDE];
    const float* wn = &ws[(8 + il) * WS_STRIDE];

    unsigned long long ar = 0ull, az = 0ull, an = 0ull;
#pragma unroll 8
    for (int k = 0; k < H_SZ; k += 4) {
        ulonglong2 h2  = *(const ulonglong2*)(hp + k);
        ulonglong2 wr2 = *(const ulonglong2*)(wr + k);
        ulonglong2 wz2 = *(const ulonglong2*)(wz + k);
        ulonglong2 wn2 = *(const ulonglong2*)(wn + k);
        ar = f2fma(h2.x, wr2.x, ar); ar = f2fma(h2.y, wr2.y, ar);
        az = f2fma(h2.x, wz2.x, az); az = f2fma(h2.y, wz2.y, az);
        an = f2fma(h2.x, wn2.x, an); an = f2fma(h2.y, wn2.y, an);
    }
    float2 pr = upk2(ar), pz = upk2(az), pn = upk2(an);
    float hr = pr.x + pr.y + b_hh[i];
    float hz = pz.x + pz.y + b_hh[H_SZ + i];
    float hn = pn.x + pn.y + b_hh[2 * H_SZ + i];

    const float* xgr = g_xg + ((size_t)b * T_SEQ + t) * G3;
    float r = sigmoidf_(xgr[i] + hr);
    float z = sigmoidf_(xgr[H_SZ + i] + hz);
    float n = tanhf(xgr[2 * H_SZ + i] + r * hn);
    float h_new = (1.0f - z) * n + z * hp[i];

    g_hs[((size_t)t * B_SZ + b) * H_SZ + i] = h_new;
}

// =====================================================================
// Kernel 3: logits GEMM (dominant)
//   out[b, t, v] = sum_k hs[t, b, k] * emb[v, k] + b_out[v]
//   A rows m = t*32 + b (hs storage order). 128x128x16 tile, f32x2.
// =====================================================================
__global__ __launch_bounds__(256, 2)
void logits_kernel(const float* __restrict__ emb,
                   const float* __restrict__ b_out,
                   float* __restrict__ out)
{
    __shared__ float As[BK * LDS_STRIDE];
    __shared__ float Bs[BK * LDS_STRIDE];

    const int tid = threadIdx.x;
    const int tx = tid & 15;
    const int ty = tid >> 4;
    const int m0 = blockIdx.x * BM;   // 0..31 tiles over 4096
    const int n0 = blockIdx.y * BN;   // 0..249 tiles over 32000

    unsigned long long acc[8][4];
#pragma unroll
    for (int i = 0; i < 8; i++)
#pragma unroll
        for (int j = 0; j < 4; j++) acc[i][j] = 0ull;

    for (int k0 = 0; k0 < H_SZ; k0 += BK) {
#pragma unroll
        for (int l = 0; l < 2; l++) {
            int f4  = tid + l * 256;
            int row = f4 >> 2;
            int c   = (f4 & 3) << 2;
            float4 v = *(const float4*)(g_hs + (size_t)(m0 + row) * H_SZ + k0 + c);
            As[(c + 0) * LDS_STRIDE + row] = v.x;
            As[(c + 1) * LDS_STRIDE + row] = v.y;
            As[(c + 2) * LDS_STRIDE + row] = v.z;
            As[(c + 3) * LDS_STRIDE + row] = v.w;
            float4 w = *(const float4*)(emb + (size_t)(n0 + row) * H_SZ + k0 + c);
            Bs[(c + 0) * LDS_STRIDE + row] = w.x;
            Bs[(c + 1) * LDS_STRIDE + row] = w.y;
            Bs[(c + 2) * LDS_STRIDE + row] = w.z;
            Bs[(c + 3) * LDS_STRIDE + row] = w.w;
        }
        __syncthreads();

#pragma unroll
        for (int kk = 0; kk < BK; kk++) {
            const float* Ak = &As[kk * LDS_STRIDE + ty * 8];
            float4 a0 = *(const float4*)(Ak);
            float4 a1 = *(const float4*)(Ak + 4);
            const float* Bk = &Bs[kk * LDS_STRIDE + tx * 8];
            ulonglong2 bl0 = *(const ulonglong2*)(Bk);
            ulonglong2 bl1 = *(const ulonglong2*)(Bk + 4);
            float av[8] = {a0.x, a0.y, a0.z, a0.w, a1.x, a1.y, a1.z, a1.w};
#pragma unroll
            for (int i = 0; i < 8; i++) {
                unsigned long long a2 = pk2(av[i], av[i]);
                acc[i][0] = f2fma(a2, bl0.x, acc[i][0]);
                acc[i][1] = f2fma(a2, bl0.y, acc[i][1]);
                acc[i][2] = f2fma(a2, bl1.x, acc[i][2]);
                acc[i][3] = f2fma(a2, bl1.y, acc[i][3]);
            }
        }
        __syncthreads();
    }

    const int vcol = n0 + tx * 8;
    float4 bo0 = *(const float4*)(b_out + vcol);
    float4 bo1 = *(const float4*)(b_out + vcol + 4);
#pragma unroll
    for (int i = 0; i < 8; i++) {
        int m = m0 + ty * 8 + i;        // m = t*32 + b
        int bb = m & 31;
        int tt = m >> 5;
        float2 p0 = upk2(acc[i][0]);
        float2 p1 = upk2(acc[i][1]);
        float2 p2 = upk2(acc[i][2]);
        float2 p3 = upk2(acc[i][3]);
        float4 o0 = {p0.x + bo0.x, p0.y + bo0.y, p1.x + bo0.z, p1.y + bo0.w};
        float4 o1 = {p2.x + bo1.x, p2.y + bo1.y, p3.x + bo1.z, p3.y + bo1.w};
        float* dst = out + ((size_t)bb * T_SEQ + tt) * V_SZ + vcol;
        *(float4*)(dst)     = o0;
        *(float4*)(dst + 4) = o1;
    }
}

// =====================================================================
// kernel_launch: embed/xg GEMM -> 128 GRU steps -> logits GEMM
// (stream-ordered, graph-capturable: kernel launches only)
// =====================================================================
extern "C" void kernel_launch(void* const* d_in, const int* in_sizes, int n_in,
                              void* d_out, int out_size)
{
    const float* emb    = (const float*)d_in[0];  // [V, H]
    const float* w_ih   = (const float*)d_in[1];  // [3H, H]
    const float* w_hh   = (const float*)d_in[2];  // [3H, H]
    const float* b_ih   = (const float*)d_in[3];  // [3H]
    const float* b_hh   = (const float*)d_in[4];  // [3H]
    const float* b_out  = (const float*)d_in[5];  // [V]
    const float* enc    = (const float*)d_in[6];  // [1, B, H]
    const int*   target = (const int*)d_in[7];    // [B, T]
    float* out = (float*)d_out;                   // [B, T, V]

    (void)in_sizes; (void)n_in; (void)out_size;

    embed_xg_kernel<<<dim3(M_ROWS / BM, G3 / BN), 256>>>(emb, w_ih, b_ih, target);

    for (int t = 0; t < T_SEQ; t++) {
        gru_step_kernel<<<128, 128>>>(t, w_hh, b_hh, enc);
    }

    logits_kernel<<<dim3(M_ROWS / BM, V_SZ / BN), 256>>>(emb, b_out, out);
}

// round 2
// speedup vs baseline: 1.0655x; 1.0655x over previous
#include <cuda_runtime.h>
#include <math.h>

// Problem constants
#define T_SEQ 128
#define B_SZ  32
#define H_SZ  512
#define V_SZ  32000
#define G3    1536          // 3*H
#define M_ROWS 4096         // B*T

// Scratch (device globals: allocation-free rule)
__device__ float g_xg[(size_t)M_ROWS * G3];         // [m = b*T+t][3H]
__device__ float g_hs[(size_t)T_SEQ * B_SZ * H_SZ]; // [t][b][h]
__device__ unsigned g_bar;                          // persistent-kernel barrier counter

// ---------- packed fp32x2 helpers (sm_10x FFMA2 path, PTX-only) ----------
static __device__ __forceinline__ unsigned long long pk2(float lo, float hi) {
    unsigned long long r;
    asm("mov.b64 %0, {%1, %2};" : "=l"(r) : "f"(lo), "f"(hi));
    return r;
}
static __device__ __forceinline__ unsigned long long f2fma(unsigned long long a,
                                                           unsigned long long b,
                                                           unsigned long long c) {
    unsigned long long d;
    asm("fma.rn.f32x2 %0, %1, %2, %3;" : "=l"(d) : "l"(a), "l"(b), "l"(c));
    return d;
}
static __device__ __forceinline__ float2 upk2(unsigned long long v) {
    float2 r;
    asm("mov.b64 {%0, %1}, %2;" : "=f"(r.x), "=f"(r.y) : "l"(v));
    return r;
}

static __device__ __forceinline__ float sigmoidf_(float x) {
    return 1.0f / (1.0f + expf(-x));
}

// =====================================================================
// Kernel 1: embed + input-gate GEMM
//   xg[m, g] = sum_k emb[tok(m), k] * w_ih[g, k] + b_ih[g]
//   tok(m):  t = m & 127; t==0 -> START(=1), else target[m-1]
// =====================================================================
#define BM 128
#define BN 128
#define BK 16
#define LDS_STRIDE 132

__global__ __launch_bounds__(256, 2)
void embed_xg_kernel(const float* __restrict__ emb,
                     const float* __restrict__ w_ih,
                     const float* __restrict__ b_ih,
                     const int*   __restrict__ target)
{
    __shared__ float As[BK * LDS_STRIDE];
    __shared__ float Bs[BK * LDS_STRIDE];

    const int tid = threadIdx.x;
    const int tx = tid & 15;
    const int ty = tid >> 4;
    const int m0 = blockIdx.x * BM;
    const int n0 = blockIdx.y * BN;

    unsigned long long acc[8][4];
#pragma unroll
    for (int i = 0; i < 8; i++)
#pragma unroll
        for (int j = 0; j < 4; j++) acc[i][j] = 0ull;

    for (int k0 = 0; k0 < H_SZ; k0 += BK) {
#pragma unroll
        for (int l = 0; l < 2; l++) {
            int f4  = tid + l * 256;
            int row = f4 >> 2;
            int c   = (f4 & 3) << 2;
            int m = m0 + row;
            int tok = (m & (T_SEQ - 1)) ? target[m - 1] : 1;
            float4 v = *(const float4*)(emb + (size_t)tok * H_SZ + k0 + c);
            As[(c + 0) * LDS_STRIDE + row] = v.x;
            As[(c + 1) * LDS_STRIDE + row] = v.y;
            As[(c + 2) * LDS_STRIDE + row] = v.z;
            As[(c + 3) * LDS_STRIDE + row] = v.w;
            int g = n0 + row;
            float4 w = *(const float4*)(w_ih + (size_t)g * H_SZ + k0 + c);
            Bs[(c + 0) * LDS_STRIDE + row] = w.x;
            Bs[(c + 1) * LDS_STRIDE + row] = w.y;
            Bs[(c + 2) * LDS_STRIDE + row] = w.z;
            Bs[(c + 3) * LDS_STRIDE + row] = w.w;
        }
        __syncthreads();

#pragma unroll
        for (int kk = 0; kk < BK; kk++) {
            const float* Ak = &As[kk * LDS_STRIDE + ty * 8];
            float4 a0 = *(const float4*)(Ak);
            float4 a1 = *(const float4*)(Ak + 4);
            const float* Bk = &Bs[kk * LDS_STRIDE + tx * 8];
            ulonglong2 bl0 = *(const ulonglong2*)(Bk);
            ulonglong2 bl1 = *(const ulonglong2*)(Bk + 4);
            float av[8] = {a0.x, a0.y, a0.z, a0.w, a1.x, a1.y, a1.z, a1.w};
#pragma unroll
            for (int i = 0; i < 8; i++) {
                unsigned long long a2 = pk2(av[i], av[i]);
                acc[i][0] = f2fma(a2, bl0.x, acc[i][0]);
                acc[i][1] = f2fma(a2, bl0.y, acc[i][1]);
                acc[i][2] = f2fma(a2, bl1.x, acc[i][2]);
                acc[i][3] = f2fma(a2, bl1.y, acc[i][3]);
            }
        }
        __syncthreads();
    }

    const int gcol = n0 + tx * 8;
    float4 bi0 = *(const float4*)(b_ih + gcol);
    float4 bi1 = *(const float4*)(b_ih + gcol + 4);
#pragma unroll
    for (int i = 0; i < 8; i++) {
        int m = m0 + ty * 8 + i;
        float2 p0 = upk2(acc[i][0]);
        float2 p1 = upk2(acc[i][1]);
        float2 p2 = upk2(acc[i][2]);
        float2 p3 = upk2(acc[i][3]);
        float4 o0 = {p0.x + bi0.x, p0.y + bi0.y, p1.x + bi0.z, p1.y + bi0.w};
        float4 o1 = {p2.x + bi1.x, p2.y + bi1.y, p3.x + bi1.z, p3.y + bi1.w};
        float* dst = g_xg + (size_t)m * G3 + gcol;
        *(float4*)(dst)     = o0;
        *(float4*)(dst + 4) = o1;
    }
}

// =====================================================================
// Barrier reset (graph-replay determinism)
// =====================================================================
__global__ void reset_bar_kernel() { g_bar = 0u; }

// =====================================================================
// Kernel 2: PERSISTENT GRU recurrence — all 128 steps in one launch.
//   128 CTAs (all co-resident on 148 SMs) x 128 threads.
//   CTA c owns H dims [4c, 4c+4): its 12 w_hh rows live in SMEM for the
//   whole kernel. Thread = (b = tid>>2, il = tid&3).
//   h_{t-1} is read from L2 with .cg loads (L1 not coherent across SMs).
//   Cross-CTA step sync: monotonic atomic counter, release/acquire.
// =====================================================================
#define WPAD 520   // 512 + 8 pad floats: rows shift 8 banks -> il groups disjoint

__global__ __launch_bounds__(128, 1)
void gru_persistent_kernel(const float* __restrict__ w_hh,
                           const float* __restrict__ b_hh,
                           const float* __restrict__ enc)
{
    __shared__ float ws[12 * WPAD];

    const int cta = blockIdx.x;     // 0..127
    const int tid = threadIdx.x;

    // Load this CTA's 12 w_hh rows once (rows: gate*512 + cta*4 + il)
#pragma unroll
    for (int l = 0; l < 12; l++) {
        int idx = tid + l * 128;         // float4 slot 0..1535
        int r   = idx >> 7;              // 0..11
        int c   = (idx & 127) << 2;      // 0..508
        int gate = r >> 2;
        int il2  = r & 3;
        int grow = gate * H_SZ + cta * 4 + il2;
        *(float4*)&ws[r * WPAD + c] = *(const float4*)(w_hh + (size_t)grow * H_SZ + c);
    }
    __syncthreads();

    const int b  = tid >> 2;
    const int il = tid & 3;
    const int i  = cta * 4 + il;

    const float bhr = b_hh[i];
    const float bhz = b_hh[H_SZ + i];
    const float bhn = b_hh[2 * H_SZ + i];

    const ulonglong2* wr = (const ulonglong2*)&ws[(0 + il) * WPAD];
    const ulonglong2* wz = (const ulonglong2*)&ws[(4 + il) * WPAD];
    const ulonglong2* wn = (const ulonglong2*)&ws[(8 + il) * WPAD];

    for (int t = 0; t < T_SEQ; t++) {
        const float* hp = (t == 0) ? (enc + b * H_SZ)
                                   : (g_hs + ((size_t)(t - 1) * B_SZ + b) * H_SZ);

        unsigned long long ar0 = 0ull, ar1 = 0ull;
        unsigned long long az0 = 0ull, az1 = 0ull;
        unsigned long long an0 = 0ull, an1 = 0ull;
#pragma unroll 8
        for (int k = 0; k < H_SZ; k += 8) {
            ulonglong2 h01 = __ldcg((const ulonglong2*)(hp + k));
            ulonglong2 h23 = __ldcg((const ulonglong2*)(hp + k + 4));
            ulonglong2 w_r0 = wr[(k >> 2) + 0];
            ulonglong2 w_r1 = wr[(k >> 2) + 1];
            ulonglong2 w_z0 = wz[(k >> 2) + 0];
            ulonglong2 w_z1 = wz[(k >> 2) + 1];
            ulonglong2 w_n0 = wn[(k >> 2) + 0];
            ulonglong2 w_n1 = wn[(k >> 2) + 1];
            ar0 = f2fma(h01.x, w_r0.x, ar0);
            ar1 = f2fma(h01.y, w_r0.y, ar1);
            ar0 = f2fma(h23.x, w_r1.x, ar0);
            ar1 = f2fma(h23.y, w_r1.y, ar1);
            az0 = f2fma(h01.x, w_z0.x, az0);
            az1 = f2fma(h01.y, w_z0.y, az1);
            az0 = f2fma(h23.x, w_z1.x, az0);
            az1 = f2fma(h23.y, w_z1.y, az1);
            an0 = f2fma(h01.x, w_n0.x, an0);
            an1 = f2fma(h01.y, w_n0.y, an1);
            an0 = f2fma(h23.x, w_n1.x, an0);
            an1 = f2fma(h23.y, w_n1.y, an1);
        }
        float2 pr0 = upk2(ar0), pr1 = upk2(ar1);
        float2 pz0 = upk2(az0), pz1 = upk2(az1);
        float2 pn0 = upk2(an0), pn1 = upk2(an1);
        float hr = (pr0.x + pr0.y) + (pr1.x + pr1.y) + bhr;
        float hz = (pz0.x + pz0.y) + (pz1.x + pz1.y) + bhz;
        float hn = (pn0.x + pn0.y) + (pn1.x + pn1.y) + bhn;

        const float* xgp = g_xg + ((size_t)b * T_SEQ + t) * G3;
        float r = sigmoidf_(xgp[i] + hr);
        float z = sigmoidf_(xgp[H_SZ + i] + hz);
        float n = tanhf(xgp[2 * H_SZ + i] + r * hn);
        float h_new = (1.0f - z) * n + z * __ldcg(hp + i);

        g_hs[((size_t)t * B_SZ + b) * H_SZ + i] = h_new;

        // ---- grid barrier (all 128 CTAs co-resident) ----
        __syncthreads();
        if (tid == 0) {
            __threadfence();                        // release h writes to L2
            atomicAdd(&g_bar, 1u);
            unsigned target = 128u * (unsigned)(t + 1);
            unsigned v;
            do {
                asm volatile("ld.acquire.gpu.u32 %0, [%1];"
                             : "=r"(v) : "l"(&g_bar) : "memory");
            } while (v < target);
        }
        __syncthreads();
    }
}

// =====================================================================
// Kernel 3: logits GEMM (dominant)
//   out[b, t, v] = sum_k hs[t, b, k] * emb[v, k] + b_out[v]
// =====================================================================
__global__ __launch_bounds__(256, 2)
void logits_kernel(const float* __restrict__ emb,
                   const float* __restrict__ b_out,
                   float* __restrict__ out)
{
    __shared__ float As[BK * LDS_STRIDE];
    __shared__ float Bs[BK * LDS_STRIDE];

    const int tid = threadIdx.x;
    const int tx = tid & 15;
    const int ty = tid >> 4;
    const int m0 = blockIdx.x * BM;
    const int n0 = blockIdx.y * BN;

    unsigned long long acc[8][4];
#pragma unroll
    for (int i = 0; i < 8; i++)
#pragma unroll
        for (int j = 0; j < 4; j++) acc[i][j] = 0ull;

    for (int k0 = 0; k0 < H_SZ; k0 += BK) {
#pragma unroll
        for (int l = 0; l < 2; l++) {
            int f4  = tid + l * 256;
            int row = f4 >> 2;
            int c   = (f4 & 3) << 2;
            float4 v = *(const float4*)(g_hs + (size_t)(m0 + row) * H_SZ + k0 + c);
            As[(c + 0) * LDS_STRIDE + row] = v.x;
            As[(c + 1) * LDS_STRIDE + row] = v.y;
            As[(c + 2) * LDS_STRIDE + row] = v.z;
            As[(c + 3) * LDS_STRIDE + row] = v.w;
            float4 w = *(const float4*)(emb + (size_t)(n0 + row) * H_SZ + k0 + c);
            Bs[(c + 0) * LDS_STRIDE + row] = w.x;
            Bs[(c + 1) * LDS_STRIDE + row] = w.y;
            Bs[(c + 2) * LDS_STRIDE + row] = w.z;
            Bs[(c + 3) * LDS_STRIDE + row] = w.w;
        }
        __syncthreads();

#pragma unroll
        for (int kk = 0; kk < BK; kk++) {
            const float* Ak = &As[kk * LDS_STRIDE + ty * 8];
            float4 a0 = *(const float4*)(Ak);
            float4 a1 = *(const float4*)(Ak + 4);
            const float* Bk = &Bs[kk * LDS_STRIDE + tx * 8];
            ulonglong2 bl0 = *(const ulonglong2*)(Bk);
            ulonglong2 bl1 = *(const ulonglong2*)(Bk + 4);
            float av[8] = {a0.x, a0.y, a0.z, a0.w, a1.x, a1.y, a1.z, a1.w};
#pragma unroll
            for (int i = 0; i < 8; i++) {
                unsigned long long a2 = pk2(av[i], av[i]);
                acc[i][0] = f2fma(a2, bl0.x, acc[i][0]);
                acc[i][1] = f2fma(a2, bl0.y, acc[i][1]);
                acc[i][2] = f2fma(a2, bl1.x, acc[i][2]);
                acc[i][3] = f2fma(a2, bl1.y, acc[i][3]);
            }
        }
        __syncthreads();
    }

    const int vcol = n0 + tx * 8;
    float4 bo0 = *(const float4*)(b_out + vcol);
    float4 bo1 = *(const float4*)(b_out + vcol + 4);
#pragma unroll
    for (int i = 0; i < 8; i++) {
        int m = m0 + ty * 8 + i;        // m = t*32 + b
        int bb = m & 31;
        int tt = m >> 5;
        float2 p0 = upk2(acc[i][0]);
        float2 p1 = upk2(acc[i][1]);
        float2 p2 = upk2(acc[i][2]);
        float2 p3 = upk2(acc[i][3]);
        float4 o0 = {p0.x + bo0.x, p0.y + bo0.y, p1.x + bo0.z, p1.y + bo0.w};
        float4 o1 = {p2.x + bo1.x, p2.y + bo1.y, p3.x + bo1.z, p3.y + bo1.w};
        float* dst = out + ((size_t)bb * T_SEQ + tt) * V_SZ + vcol;
        *(float4*)(dst)     = o0;
        *(float4*)(dst + 4) = o1;
    }
}

// =====================================================================
// kernel_launch: embed/xg GEMM -> barrier reset -> persistent GRU -> logits
// =====================================================================
extern "C" void kernel_launch(void* const* d_in, const int* in_sizes, int n_in,
                              void* d_out, int out_size)
{
    const float* emb    = (const float*)d_in[0];  // [V, H]
    const float* w_ih   = (const float*)d_in[1];  // [3H, H]
    const float* w_hh   = (const float*)d_in[2];  // [3H, H]
    const float* b_ih   = (const float*)d_in[3];  // [3H]
    const float* b_hh   = (const float*)d_in[4];  // [3H]
    const float* b_out  = (const float*)d_in[5];  // [V]
    const float* enc    = (const float*)d_in[6];  // [1, B, H]
    const int*   target = (const int*)d_in[7];    // [B, T]
    float* out = (float*)d_out;                   // [B, T, V]

    (void)in_sizes; (void)n_in; (void)out_size;

    embed_xg_kernel<<<dim3(M_ROWS / BM, G3 / BN), 256>>>(emb, w_ih, b_ih, target);

    reset_bar_kernel<<<1, 1>>>();
    gru_persistent_kernel<<<128, 128>>>(w_hh, b_hh, enc);

    logits_kernel<<<dim3(M_ROWS / BM, V_SZ / BN), 256>>>(emb, b_out, out);
}

// round 4
// speedup vs baseline: 1.8287x; 1.7163x over previous
#include <cuda_runtime.h>
#include <cuda_bf16.h>
#include <math.h>
#include <stdint.h>

// Problem constants
#define T_SEQ 128
#define B_SZ  32
#define H_SZ  512
#define V_SZ  32000
#define G3    1536          // 3*H
#define M_ROWS 4096         // B*T
#define KSPLIT 1536         // folded K: [hi|hi|lo] x [hi|lo|hi]

// Scratch (device globals: allocation-free rule)
__device__ __align__(16) float g_xg[(size_t)M_ROWS * G3];          // [m=b*T+t][3H]
__device__ __align__(16) float g_hs[(size_t)T_SEQ * B_SZ * H_SZ];  // [t][b][h]
__device__ __align__(16) __nv_bfloat16 g_ab[(size_t)M_ROWS * KSPLIT];  // A'
__device__ __align__(16) __nv_bfloat16 g_bb[(size_t)V_SZ * KSPLIT];    // B'
__device__ unsigned g_bar;

// ---------- packed fp32x2 helpers ----------
static __device__ __forceinline__ unsigned long long pk2(float lo, float hi) {
    unsigned long long r;
    asm("mov.b64 %0, {%1, %2};" : "=l"(r) : "f"(lo), "f"(hi));
    return r;
}
static __device__ __forceinline__ unsigned long long f2fma(unsigned long long a,
                                                           unsigned long long b,
                                                           unsigned long long c) {
    unsigned long long d;
    asm("fma.rn.f32x2 %0, %1, %2, %3;" : "=l"(d) : "l"(a), "l"(b), "l"(c));
    return d;
}
static __device__ __forceinline__ float2 upk2(unsigned long long v) {
    float2 r;
    asm("mov.b64 {%0, %1}, %2;" : "=f"(r.x), "=f"(r.y) : "l"(v));
    return r;
}
static __device__ __forceinline__ float sigmoidf_(float x) {
    return 1.0f / (1.0f + expf(-x));
}

// ---------- smem / async-copy / mma helpers (baseline PTX only) ----------
static __device__ __forceinline__ uint32_t smem_u32(const void* p) {
    uint32_t a;
    asm("{ .reg .u64 t; cvta.to.shared.u64 t, %1; cvt.u32.u64 %0, t; }"
        : "=r"(a) : "l"(p));
    return a;
}
static __device__ __forceinline__ void cp_async16(uint32_t dst, const void* src) {
    asm volatile("cp.async.cg.shared.global [%0], [%1], 16;" :: "r"(dst), "l"(src));
}
static __device__ __forceinline__ void cp_commit() {
    asm volatile("cp.async.commit_group;");
}
static __device__ __forceinline__ void cp_wait1() {
    asm volatile("cp.async.wait_group 1;" ::: "memory");
}
static __device__ __forceinline__ void ldsm4(uint32_t* r, uint32_t addr) {
    asm volatile("ldmatrix.sync.aligned.m8n8.x4.shared.b16 {%0,%1,%2,%3}, [%4];"
                 : "=r"(r[0]), "=r"(r[1]), "=r"(r[2]), "=r"(r[3]) : "r"(addr));
}
static __device__ __forceinline__ void mma16816(float* c, const uint32_t* a,
                                                uint32_t b0, uint32_t b1) {
    asm volatile(
        "mma.sync.aligned.m16n8k16.row.col.f32.bf16.bf16.f32 "
        "{%0,%1,%2,%3}, {%4,%5,%6,%7}, {%8,%9}, {%0,%1,%2,%3};"
        : "+f"(c[0]), "+f"(c[1]), "+f"(c[2]), "+f"(c[3])
        : "r"(a[0]), "r"(a[1]), "r"(a[2]), "r"(a[3]), "r"(b0), "r"(b1));
}

// =====================================================================
// Kernel 1: embed + input-gate GEMM (fp32 FFMA2)
// =====================================================================
#define BM 128
#define BN 128
#define BK 16
#define LDS_STRIDE 132

__global__ __launch_bounds__(256, 2)
void embed_xg_kernel(const float* __restrict__ emb,
                     const float* __restrict__ w_ih,
                     const float* __restrict__ b_ih,
                     const int*   __restrict__ target)
{
    __shared__ float As[BK * LDS_STRIDE];
    __shared__ float Bs[BK * LDS_STRIDE];

    const int tid = threadIdx.x;
    const int tx = tid & 15;
    const int ty = tid >> 4;
    const int m0 = blockIdx.x * BM;
    const int n0 = blockIdx.y * BN;

    unsigned long long acc[8][4];
#pragma unroll
    for (int i = 0; i < 8; i++)
#pragma unroll
        for (int j = 0; j < 4; j++) acc[i][j] = 0ull;

    for (int k0 = 0; k0 < H_SZ; k0 += BK) {
#pragma unroll
        for (int l = 0; l < 2; l++) {
            int f4  = tid + l * 256;
            int row = f4 >> 2;
            int c   = (f4 & 3) << 2;
            int m = m0 + row;
            int tok = (m & (T_SEQ - 1)) ? target[m - 1] : 1;
            float4 v = *(const float4*)(emb + (size_t)tok * H_SZ + k0 + c);
            As[(c + 0) * LDS_STRIDE + row] = v.x;
            As[(c + 1) * LDS_STRIDE + row] = v.y;
            As[(c + 2) * LDS_STRIDE + row] = v.z;
            As[(c + 3) * LDS_STRIDE + row] = v.w;
            int g = n0 + row;
            float4 w = *(const float4*)(w_ih + (size_t)g * H_SZ + k0 + c);
            Bs[(c + 0) * LDS_STRIDE + row] = w.x;
            Bs[(c + 1) * LDS_STRIDE + row] = w.y;
            Bs[(c + 2) * LDS_STRIDE + row] = w.z;
            Bs[(c + 3) * LDS_STRIDE + row] = w.w;
        }
        __syncthreads();

#pragma unroll
        for (int kk = 0; kk < BK; kk++) {
            const float* Ak = &As[kk * LDS_STRIDE + ty * 8];
            float4 a0 = *(const float4*)(Ak);
            float4 a1 = *(const float4*)(Ak + 4);
            const float* Bk = &Bs[kk * LDS_STRIDE + tx * 8];
            ulonglong2 bl0 = *(const ulonglong2*)(Bk);
            ulonglong2 bl1 = *(const ulonglong2*)(Bk + 4);
            float av[8] = {a0.x, a0.y, a0.z, a0.w, a1.x, a1.y, a1.z, a1.w};
#pragma unroll
            for (int i = 0; i < 8; i++) {
                unsigned long long a2 = pk2(av[i], av[i]);
                acc[i][0] = f2fma(a2, bl0.x, acc[i][0]);
                acc[i][1] = f2fma(a2, bl0.y, acc[i][1]);
                acc[i][2] = f2fma(a2, bl1.x, acc[i][2]);
                acc[i][3] = f2fma(a2, bl1.y, acc[i][3]);
            }
        }
        __syncthreads();
    }

    const int gcol = n0 + tx * 8;
    float4 bi0 = *(const float4*)(b_ih + gcol);
    float4 bi1 = *(const float4*)(b_ih + gcol + 4);
#pragma unroll
    for (int i = 0; i < 8; i++) {
        int m = m0 + ty * 8 + i;
        float2 p0 = upk2(acc[i][0]);
        float2 p1 = upk2(acc[i][1]);
        float2 p2 = upk2(acc[i][2]);
        float2 p3 = upk2(acc[i][3]);
        float4 o0 = {p0.x + bi0.x, p0.y + bi0.y, p1.x + bi0.z, p1.y + bi0.w};
        float4 o1 = {p2.x + bi1.x, p2.y + bi1.y, p3.x + bi1.z, p3.y + bi1.w};
        float* dst = g_xg + (size_t)m * G3 + gcol;
        *(float4*)(dst)     = o0;
        *(float4*)(dst + 4) = o1;
    }
}

// =====================================================================
// Barrier reset
// =====================================================================
__global__ void reset_bar_kernel() { g_bar = 0u; }

// =====================================================================
// Kernel 2: persistent GRU — h staged into SMEM per step.
// =====================================================================
#define WPAD 520
#define HPAD 516

__global__ __launch_bounds__(128, 1)
void gru_persistent_kernel(const float* __restrict__ w_hh,
                           const float* __restrict__ b_hh,
                           const float* __restrict__ enc)
{
    extern __shared__ float dsm[];
    float* ws  = dsm;                  // 12 * WPAD
    float* hsm = dsm + 12 * WPAD;      // 32 * HPAD

    const int cta = blockIdx.x;
    const int tid = threadIdx.x;

#pragma unroll
    for (int l = 0; l < 12; l++) {
        int idx = tid + l * 128;
        int r   = idx >> 7;
        int c   = (idx & 127) << 2;
        int gate = r >> 2;
        int il2  = r & 3;
        int grow = gate * H_SZ + cta * 4 + il2;
        *(float4*)&ws[r * WPAD + c] = *(const float4*)(w_hh + (size_t)grow * H_SZ + c);
    }

    const int b  = tid >> 2;
    const int il = tid & 3;
    const int i  = cta * 4 + il;

    const float bhr = b_hh[i];
    const float bhz = b_hh[H_SZ + i];
    const float bhn = b_hh[2 * H_SZ + i];

    const ulonglong2* wr = (const ulonglong2*)&ws[(0 + il) * WPAD];
    const ulonglong2* wz = (const ulonglong2*)&ws[(4 + il) * WPAD];
    const ulonglong2* wn = (const ulonglong2*)&ws[(8 + il) * WPAD];

    for (int t = 0; t < T_SEQ; t++) {
        const float* hsrc = (t == 0) ? enc : (g_hs + (size_t)(t - 1) * B_SZ * H_SZ);
        __syncthreads();
#pragma unroll
        for (int j = 0; j < 32; j++) {
            int s  = tid + j * 128;
            int bb = s >> 7;
            int k4 = (s & 127) << 2;
            float4 v = __ldcg((const float4*)(hsrc + (size_t)bb * H_SZ + k4));
            *(float4*)&hsm[bb * HPAD + k4] = v;
        }
        __syncthreads();

        const float* hp = &hsm[b * HPAD];
        unsigned long long ar0 = 0ull, ar1 = 0ull;
        unsigned long long az0 = 0ull, az1 = 0ull;
        unsigned long long an0 = 0ull, an1 = 0ull;
#pragma unroll 8
        for (int k = 0; k < H_SZ; k += 8) {
            ulonglong2 h01 = *(const ulonglong2*)(hp + k);
            ulonglong2 h23 = *(const ulonglong2*)(hp + k + 4);
            ulonglong2 w_r0 = wr[(k >> 2) + 0];
            ulonglong2 w_r1 = wr[(k >> 2) + 1];
            ulonglong2 w_z0 = wz[(k >> 2) + 0];
            ulonglong2 w_z1 = wz[(k >> 2) + 1];
            ulonglong2 w_n0 = wn[(k >> 2) + 0];
            ulonglong2 w_n1 = wn[(k >> 2) + 1];
            ar0 = f2fma(h01.x, w_r0.x, ar0);
            ar1 = f2fma(h01.y, w_r0.y, ar1);
            ar0 = f2fma(h23.x, w_r1.x, ar0);
            ar1 = f2fma(h23.y, w_r1.y, ar1);
            az0 = f2fma(h01.x, w_z0.x, az0);
            az1 = f2fma(h01.y, w_z0.y, az1);
            az0 = f2fma(h23.x, w_z1.x, az0);
            az1 = f2fma(h23.y, w_z1.y, az1);
            an0 = f2fma(h01.x, w_n0.x, an0);
            an1 = f2fma(h01.y, w_n0.y, an1);
            an0 = f2fma(h23.x, w_n1.x, an0);
            an1 = f2fma(h23.y, w_n1.y, an1);
        }
        float2 pr0 = upk2(ar0), pr1 = upk2(ar1);
        float2 pz0 = upk2(az0), pz1 = upk2(az1);
        float2 pn0 = upk2(an0), pn1 = upk2(an1);
        float hr = (pr0.x + pr0.y) + (pr1.x + pr1.y) + bhr;
        float hz = (pz0.x + pz0.y) + (pz1.x + pz1.y) + bhz;
        float hn = (pn0.x + pn0.y) + (pn1.x + pn1.y) + bhn;

        const float* xgp = g_xg + ((size_t)b * T_SEQ + t) * G3;
        float r = sigmoidf_(xgp[i] + hr);
        float z = sigmoidf_(xgp[H_SZ + i] + hz);
        float n = tanhf(xgp[2 * H_SZ + i] + r * hn);
        float h_new = (1.0f - z) * n + z * hp[i];

        g_hs[((size_t)t * B_SZ + b) * H_SZ + i] = h_new;

        __syncthreads();
        if (tid == 0) {
            __threadfence();
            atomicAdd(&g_bar, 1u);
            unsigned tgt = 128u * (unsigned)(t + 1);
            unsigned v;
            do {
                asm volatile("ld.acquire.gpu.u32 %0, [%1];"
                             : "=r"(v) : "l"(&g_bar) : "memory");
            } while (v < tgt);
        }
        __syncthreads();
    }
}

// =====================================================================
// Conversion kernels: fp32 -> bf16 hi/lo split, folded-K layout
// =====================================================================
union BF4 { __nv_bfloat16 h[4]; uint2 u; };

static __device__ __forceinline__ void split4(float4 x, BF4& hi, BF4& lo) {
    hi.h[0] = __float2bfloat16_rn(x.x);
    hi.h[1] = __float2bfloat16_rn(x.y);
    hi.h[2] = __float2bfloat16_rn(x.z);
    hi.h[3] = __float2bfloat16_rn(x.w);
    lo.h[0] = __float2bfloat16_rn(x.x - __bfloat162float(hi.h[0]));
    lo.h[1] = __float2bfloat16_rn(x.y - __bfloat162float(hi.h[1]));
    lo.h[2] = __float2bfloat16_rn(x.z - __bfloat162float(hi.h[2]));
    lo.h[3] = __float2bfloat16_rn(x.w - __bfloat162float(hi.h[3]));
}

__global__ __launch_bounds__(256)
void convert_emb_kernel(const float* __restrict__ emb)
{
    int s = blockIdx.x * 256 + threadIdx.x;
    if (s >= V_SZ * (H_SZ / 4)) return;
    int v  = s >> 7;
    int k4 = (s & 127) << 2;
    float4 x = *(const float4*)(emb + (size_t)v * H_SZ + k4);
    BF4 hi, lo;
    split4(x, hi, lo);
    __nv_bfloat16* row = g_bb + (size_t)v * KSPLIT;
    *(uint2*)(row + k4)        = hi.u;   // seg0: hi
    *(uint2*)(row + 512 + k4)  = lo.u;   // seg1: lo
    *(uint2*)(row + 1024 + k4) = hi.u;   // seg2: hi
}

__global__ __launch_bounds__(256)
void convert_hs_kernel()
{
    int s = blockIdx.x * 256 + threadIdx.x;
    if (s >= M_ROWS * (H_SZ / 4)) return;
    int m  = s >> 7;
    int k4 = (s & 127) << 2;
    float4 x = *(const float4*)(g_hs + (size_t)m * H_SZ + k4);
    BF4 hi, lo;
    split4(x, hi, lo);
    __nv_bfloat16* row = g_ab + (size_t)m * KSPLIT;
    *(uint2*)(row + k4)        = hi.u;   // seg0: hi
    *(uint2*)(row + 512 + k4)  = hi.u;   // seg1: hi
    *(uint2*)(row + 1024 + k4) = lo.u;   // seg2: lo
}

// =====================================================================
// Kernel 3: logits GEMM via mma.sync bf16 (baseline PTX, HMMA)
//   out[b, t, v] = sum_k' A'[m][k'] * B'[v][k'] + b_out[v],  m = t*32+b
//   CTA 128x128, 8 warps (2x4), warp 64x32, K chunks of 32, 3-stage cp.async.
// =====================================================================
#define LMT 128
#define LNT 128
#define CHK 32
#define NCH (KSPLIT / CHK)     // 48
#define STAGES 3
#define AROWB 80               // bytes per smem row: 32 bf16 + 8 pad
#define ATILE_B (128 * AROWB)  // 10240
#define STAGE_B (2 * ATILE_B)  // 20480  (A then B)
#define LTOT_B (STAGES * STAGE_B)  // 61440

__global__ __launch_bounds__(256, 2)
void logits_mma_kernel(const float* __restrict__ b_out,
                       float* __restrict__ out)
{
    extern __shared__ __align__(128) char lsm[];
    const uint32_t smb = smem_u32(lsm);
    const int tid  = threadIdx.x;
    const int wid  = tid >> 5;
    const int lane = tid & 31;
    const int warp_m = wid >> 2;   // 0..1
    const int warp_n = wid & 3;    // 0..3
    const int m0 = blockIdx.x * LMT;
    const int n0 = blockIdx.y * LNT;

    // loader mapping: 2 x (row, seg) per array per stage
    const int lr0 = tid >> 2;            // 0..63
    const int lsg = (tid & 3) * 16;      // byte seg 0,16,32,48

    float c[4][4][4];
#pragma unroll
    for (int i = 0; i < 4; i++)
#pragma unroll
        for (int j = 0; j < 4; j++)
#pragma unroll
            for (int q = 0; q < 4; q++) c[i][j][q] = 0.0f;

    // ldmatrix lane addressing: row = lane&15, 16B-half = lane>>4
    const int lrow = lane & 15;
    const int lkh  = (lane >> 4) * 16;

    // ---- prologue: issue stages 0,1 ----
#pragma unroll
    for (int ch = 0; ch < 2; ch++) {
        uint32_t As = smb + ch * STAGE_B;
        uint32_t Bs = As + ATILE_B;
        const __nv_bfloat16* ag = g_ab + (size_t)(m0) * KSPLIT + ch * CHK;
        const __nv_bfloat16* bg = g_bb + (size_t)(n0) * KSPLIT + ch * CHK;
#pragma unroll
        for (int l = 0; l < 2; l++) {
            int r = lr0 + l * 64;
            cp_async16(As + r * AROWB + lsg, ag + (size_t)r * KSPLIT + (lsg >> 1));
            cp_async16(Bs + r * AROWB + lsg, bg + (size_t)r * KSPLIT + (lsg >> 1));
        }
        cp_commit();
    }

    for (int ch = 0; ch < NCH; ch++) {
        cp_wait1();
        __syncthreads();

        // issue ch+2 (stage reuses (ch-1)%3, free after the barrier above)
        {
            int chn = ch + 2;
            uint32_t As = smb + (chn % STAGES) * STAGE_B;
            uint32_t Bs = As + ATILE_B;
            if (chn < NCH) {
                const __nv_bfloat16* ag = g_ab + (size_t)m0 * KSPLIT + chn * CHK;
                const __nv_bfloat16* bg = g_bb + (size_t)n0 * KSPLIT + chn * CHK;
#pragma unroll
                for (int l = 0; l < 2; l++) {
                    int r = lr0 + l * 64;
                    cp_async16(As + r * AROWB + lsg, ag + (size_t)r * KSPLIT + (lsg >> 1));
                    cp_async16(Bs + r * AROWB + lsg, bg + (size_t)r * KSPLIT + (lsg >> 1));
                }
            }
            cp_commit();   // empty groups keep wait_group counting aligned
        }

        // compute on stage ch%3
        uint32_t As = smb + (ch % STAGES) * STAGE_B;
        uint32_t Bs = As + ATILE_B;
        uint32_t a_base = As + (warp_m * 64 + lrow) * AROWB + lkh;
        uint32_t b_base = Bs + (warp_n * 32 + lrow) * AROWB + lkh;

#pragma unroll
        for (int ks = 0; ks < 2; ks++) {
            uint32_t a[4][4], bb[2][4];
#pragma unroll
            for (int mt = 0; mt < 4; mt++)
                ldsm4(a[mt], a_base + mt * 16 * AROWB + ks * 32);
#pragma unroll
            for (int np = 0; np < 2; np++)
                ldsm4(bb[np], b_base + np * 16 * AROWB + ks * 32);
#pragma unroll
            for (int mt = 0; mt < 4; mt++) {
#pragma unroll
                for (int nt = 0; nt < 4; nt++) {
                    uint32_t* bv = bb[nt >> 1];
                    mma16816(c[mt][nt], a[mt], bv[nt & 1], bv[(nt & 1) + 2]);
                }
            }
        }
        __syncthreads();
    }

    // ---- epilogue ----
    const int r    = lane >> 2;
    const int col2 = (lane & 3) * 2;
    const int ncol0 = n0 + warp_n * 32;
#pragma unroll
    for (int mt = 0; mt < 4; mt++) {
#pragma unroll
        for (int half = 0; half < 2; half++) {
            int m = m0 + warp_m * 64 + mt * 16 + r + half * 8;
            int bb2 = m & 31;
            int tt  = m >> 5;
            float* dst = out + ((size_t)bb2 * T_SEQ + tt) * V_SZ + ncol0;
#pragma unroll
            for (int nt = 0; nt < 4; nt++) {
                int nc = nt * 8 + col2;
                float2 v;
                v.x = c[mt][nt][half * 2 + 0] + __ldg(b_out + ncol0 + nc);
                v.y = c[mt][nt][half * 2 + 1] + __ldg(b_out + ncol0 + nc + 1);
                *(float2*)(dst + nc) = v;
            }
        }
    }
}

// =====================================================================
// kernel_launch
// =====================================================================
extern "C" void kernel_launch(void* const* d_in, const int* in_sizes, int n_in,
                              void* d_out, int out_size)
{
    const float* emb    = (const float*)d_in[0];  // [V, H]
    const float* w_ih   = (const float*)d_in[1];  // [3H, H]
    const float* w_hh   = (const float*)d_in[2];  // [3H, H]
    const float* b_ih   = (const float*)d_in[3];  // [3H]
    const float* b_hh   = (const float*)d_in[4];  // [3H]
    const float* b_out  = (const float*)d_in[5];  // [V]
    const float* enc    = (const float*)d_in[6];  // [1, B, H]
    const int*   target = (const int*)d_in[7];    // [B, T]
    float* out = (float*)d_out;                   // [B, T, V]

    (void)in_sizes; (void)n_in; (void)out_size;

    static bool attr_done = false;
    if (!attr_done) {
        cudaFuncSetAttribute(gru_persistent_kernel,
                             cudaFuncAttributeMaxDynamicSharedMemorySize,
                             (12 * WPAD + 32 * HPAD) * sizeof(float));
        cudaFuncSetAttribute(logits_mma_kernel,
                             cudaFuncAttributeMaxDynamicSharedMemorySize, LTOT_B);
        attr_done = true;
    }

    convert_emb_kernel<<<(V_SZ * (H_SZ / 4) + 255) / 256, 256>>>(emb);

    embed_xg_kernel<<<dim3(M_ROWS / BM, G3 / BN), 256>>>(emb, w_ih, b_ih, target);

    reset_bar_kernel<<<1, 1>>>();
    gru_persistent_kernel<<<128, 128, (12 * WPAD + 32 * HPAD) * sizeof(float)>>>(
        w_hh, b_hh, enc);

    convert_hs_kernel<<<(M_ROWS * (H_SZ / 4) + 255) / 256, 256>>>();

    logits_mma_kernel<<<dim3(M_ROWS / LMT, V_SZ / LNT), 256, LTOT_B>>>(b_out, out);
}